// round 12
// baseline (speedup 1.0000x reference)
#include <cuda_runtime.h>
#include <cuda_bf16.h>
#include <math.h>

#define BATCH   8
#define NPTS    8192
#define NPOINT  2048
#define NSAMPLE 32

#define NCONS   140          // consumer CTAs (grid = 8 + 140 = 148 <= SM count)
#define NTILES  4096         // BATCH*NPOINT/4 centroids per tile

// ---------------- scratch (no allocation allowed) ----------------
__device__ int g_progress[BATCH];      // fps progress per batch (reset by prep)
// bf16 split weights, K-concatenated [hiB | hiB | loB] (+zero pad), n-major rows
__device__ __align__(16) __nv_bfloat16 g_wb1[64 * 232];   // K'=204 (68x3), stride 232
__device__ __align__(16) __nv_bfloat16 g_wb2[64 * 200];   // K'=192, stride 200
__device__ __align__(16) __nv_bfloat16 g_wb3[128 * 200];
__device__ float g_fb1[64];
__device__ float g_fb2[64];
__device__ float g_fb3[128];

// ---------------- packed f32x2 helpers (per-lane rn => bitwise == scalar) ---
__device__ __forceinline__ unsigned long long pk2(float lo, float hi) {
    unsigned long long r;
    asm("mov.b64 %0, {%1, %2};" : "=l"(r) : "f"(lo), "f"(hi));
    return r;
}
__device__ __forceinline__ void upk2(float& lo, float& hi, unsigned long long v) {
    asm("mov.b64 {%0, %1}, %2;" : "=f"(lo), "=f"(hi) : "l"(v));
}
__device__ __forceinline__ unsigned long long add2(unsigned long long a, unsigned long long b) {
    unsigned long long r;
    asm("add.rn.f32x2 %0, %1, %2;" : "=l"(r) : "l"(a), "l"(b));
    return r;
}
__device__ __forceinline__ unsigned long long mul2(unsigned long long a, unsigned long long b) {
    unsigned long long r;
    asm("mul.rn.f32x2 %0, %1, %2;" : "=l"(r) : "l"(a), "l"(b));
    return r;
}

// ---------------- sync / load helpers ----------------
__device__ __forceinline__ int ld_acq(const int* p) {
    int v;
    asm volatile("ld.acquire.gpu.global.b32 %0, [%1];" : "=r"(v) : "l"(p) : "memory");
    return v;
}
__device__ __forceinline__ void st_rel(int* p, int v) {
    asm volatile("st.release.gpu.global.b32 [%0], %1;" :: "l"(p), "r"(v) : "memory");
}
__device__ __forceinline__ float ldcg(const float* p) {
    float v;
    asm volatile("ld.global.cg.f32 %0, [%1];" : "=f"(v) : "l"(p));
    return v;
}

// ---------------- mma / ldmatrix helpers ----------------
#define LDSM4(a0,a1,a2,a3,addr) \
    asm volatile("ldmatrix.sync.aligned.m8n8.x4.shared.b16 {%0,%1,%2,%3}, [%4];" \
        : "=r"(a0), "=r"(a1), "=r"(a2), "=r"(a3) : "r"(addr))
#define MMA_BF16(d0,d1,d2,d3,a0,a1,a2,a3,b0,b1) \
    asm volatile("mma.sync.aligned.m16n8k16.row.col.f32.bf16.bf16.f32 " \
        "{%0,%1,%2,%3},{%4,%5,%6,%7},{%8,%9},{%0,%1,%2,%3};" \
        : "+f"(d0), "+f"(d1), "+f"(d2), "+f"(d3) \
        : "r"(a0), "r"(a1), "r"(a2), "r"(a3), "r"(b0), "r"(b1))

// ---------------- fold BN-affine into bf16 hi/lo split weights ----------------
__global__ void prep_kernel(const float* __restrict__ w1, const float* __restrict__ b1,
                            const float* __restrict__ g1, const float* __restrict__ bt1,
                            const float* __restrict__ w2, const float* __restrict__ b2,
                            const float* __restrict__ g2, const float* __restrict__ bt2,
                            const float* __restrict__ w3, const float* __restrict__ b3,
                            const float* __restrict__ g3, const float* __restrict__ bt3)
{
    int t = blockIdx.x * blockDim.x + threadIdx.x;
    int stride = gridDim.x * blockDim.x;
    const float inv = 1.0f / sqrtf(1.0f + 1e-5f);
    for (int i = t; i < BATCH; i += stride) g_progress[i] = 0;   // reset each launch
    for (int i = t; i < 64 * 232; i += stride) {
        int o = i / 232, c = i % 232;
        __nv_bfloat16 outv = __float2bfloat16_rn(0.0f);
        if (c < 204) {
            int k = c % 68, seg = c / 68;
            float v = (k < 67) ? (g1[o] * inv) * w1[o * 67 + k] : 0.0f;
            __nv_bfloat16 hi = __float2bfloat16_rn(v);
            if (seg < 2) outv = hi;
            else         outv = __float2bfloat16_rn(v - __bfloat162float(hi));
        }
        g_wb1[i] = outv;
    }
    for (int i = t; i < 64 * 200; i += stride) {
        int o = i / 200, c = i % 200;
        __nv_bfloat16 outv = __float2bfloat16_rn(0.0f);
        if (c < 192) {
            int k = c & 63, seg = c >> 6;
            float v = (g2[o] * inv) * w2[o * 64 + k];
            __nv_bfloat16 hi = __float2bfloat16_rn(v);
            if (seg < 2) outv = hi;
            else         outv = __float2bfloat16_rn(v - __bfloat162float(hi));
        }
        g_wb2[i] = outv;
    }
    for (int i = t; i < 128 * 200; i += stride) {
        int o = i / 200, c = i % 200;
        __nv_bfloat16 outv = __float2bfloat16_rn(0.0f);
        if (c < 192) {
            int k = c & 63, seg = c >> 6;
            float v = (g3[o] * inv) * w3[o * 64 + k];
            __nv_bfloat16 hi = __float2bfloat16_rn(v);
            if (seg < 2) outv = hi;
            else         outv = __float2bfloat16_rn(v - __bfloat162float(hi));
        }
        g_wb3[i] = outv;
    }
    for (int i = t; i < 64; i += stride) {
        g_fb1[i] = (g1[i] * inv) * b1[i] + bt1[i];
        g_fb2[i] = (g2[i] * inv) * b2[i] + bt2[i];
    }
    for (int i = t; i < 128; i += stride)
        g_fb3[i] = (g3[i] * inv) * b3[i] + bt3[i];
}

// ---------------- fused persistent kernel layout ----------------
// smem byte offsets (all 16B aligned). FPS path uses [0, 98304) only.
#define SM_A1   0                    // 128 x 464B (layer1 A), reused stride 400B as y2
#define SM_A2   59392                // 128 x 400B
#define SM_B1   110592               // 64 x 464B
#define SM_B2   140288               // 64 x 400B
#define SM_B3   165888               // 128 x 400B
#define SM_SB1  217088
#define SM_SB2  217344
#define SM_SB3  217600
#define SM_PB   218112               // 4 x 128 int
#define SM_SIDX 220160               // 4 x 32 int (ball indices)
#define SM_CC   220672               // 4 x 3 float centroid coords (+pad)
#define SM_TOT  220736

// K'-loop over this warp's 4 n-tiles (two ldmatrix.x4 B loads per k-step).
template<int KSTEPS>
__device__ __forceinline__ void gemm_4nt(unsigned aAddr, unsigned bAddr0, unsigned bAddr1,
                                         const float* __restrict__ bias, int lane,
                                         float (*acc)[4])
{
    int cp2 = 2 * (lane & 3);
#pragma unroll
    for (int ntl = 0; ntl < 4; ntl++) {
        float bv0 = bias[8 * ntl + cp2];
        float bv1 = bias[8 * ntl + cp2 + 1];
        acc[ntl][0] = bv0; acc[ntl][1] = bv1; acc[ntl][2] = bv0; acc[ntl][3] = bv1;
    }
#pragma unroll
    for (int ks = 0; ks < KSTEPS; ks++) {
        unsigned a0, a1, a2, a3;
        LDSM4(a0, a1, a2, a3, aAddr);
        aAddr += 32;
        unsigned p0, p1, p2, p3, q0, q1, q2, q3;
        LDSM4(p0, p1, p2, p3, bAddr0);  bAddr0 += 32;
        LDSM4(q0, q1, q2, q3, bAddr1);  bAddr1 += 32;
        MMA_BF16(acc[0][0], acc[0][1], acc[0][2], acc[0][3], a0, a1, a2, a3, p0, p1);
        MMA_BF16(acc[1][0], acc[1][1], acc[1][2], acc[1][3], a0, a1, a2, a3, p2, p3);
        MMA_BF16(acc[2][0], acc[2][1], acc[2][2], acc[2][3], a0, a1, a2, a3, q0, q1);
        MMA_BF16(acc[3][0], acc[3][1], acc[3][2], acc[3][3], a0, a1, a2, a3, q2, q3);
    }
}

// relu + bf16 hi/lo re-split + store into next layer's A' (stride 400B).
__device__ __forceinline__ void epi_split4(char* __restrict__ outBase, int mt, int nh,
                                           int lane, float (*acc)[4])
{
    int rr = lane >> 2, cpl = lane & 3;
#pragma unroll
    for (int ntl = 0; ntl < 4; ntl++) {
        int nt = 4 * nh + ntl;
        float v0 = fmaxf(acc[ntl][0], 0.0f), v1 = fmaxf(acc[ntl][1], 0.0f);
        float v2 = fmaxf(acc[ntl][2], 0.0f), v3 = fmaxf(acc[ntl][3], 0.0f);
        __nv_bfloat162 h01 = __floats2bfloat162_rn(v0, v1);
        __nv_bfloat162 h23 = __floats2bfloat162_rn(v2, v3);
        float2 hf01 = __bfloat1622float2(h01);
        float2 hf23 = __bfloat1622float2(h23);
        __nv_bfloat162 l01 = __floats2bfloat162_rn(v0 - hf01.x, v1 - hf01.y);
        __nv_bfloat162 l23 = __floats2bfloat162_rn(v2 - hf23.x, v3 - hf23.y);
        int off0 = (16 * mt + rr) * 400 + (4 * nt + cpl) * 4;
        int off1 = off0 + 8 * 400;
        *(__nv_bfloat162*)(outBase + off0)       = h01;   // hi seg
        *(__nv_bfloat162*)(outBase + off0 + 128) = l01;   // lo seg
        *(__nv_bfloat162*)(outBase + off0 + 256) = h01;   // hi dup
        *(__nv_bfloat162*)(outBase + off1)       = h23;
        *(__nv_bfloat162*)(outBase + off1 + 128) = l23;
        *(__nv_bfloat162*)(outBase + off1 + 256) = h23;
    }
}

// ---------------- fused persistent kernel ----------------
// Blocks 0..7: FPS producers (one batch each, bitwise-exact distance math;
// release g_progress[b]=it+1 after each centroid store).
// Blocks 8..147: persistent consumers over NTILES 4-centroid tiles:
// acquire-poll progress -> inline ball query (results stay in smem) ->
// gather -> 3-layer split-bf16 tensor-core MLP -> fused relu+max-pool.
// Grid 148 <= SM count and 1 CTA/SM -> all CTAs resident in wave 1 (no deadlock).
__global__ void __launch_bounds__(512, 1)
fused_kernel(const float* __restrict__ xyz, const float* __restrict__ feats,
             float* __restrict__ out_xyz, float* __restrict__ out_feats)
{
    extern __shared__ char smem[];
    __shared__ unsigned red_v[2][16];
    __shared__ int      red_i[2][16];

    int tid = threadIdx.x, lane = tid & 31, w = tid >> 5;

    if (blockIdx.x < BATCH) {
        // ================= FPS producer =================
        float* sx = (float*)smem;
        float* sy = sx + NPTS;
        float* sz = sy + NPTS;
        int b = blockIdx.x;
        const float* xb = xyz + (size_t)b * NPTS * 3;

        for (int p = tid; p < NPTS; p += 512) {
            sx[p] = xb[3 * p];
            sy[p] = xb[3 * p + 1];
            sz[p] = xb[3 * p + 2];
        }
        __syncthreads();

        int base = tid * 16;
        unsigned long long pxp[8], pyp[8], pzp[8];
        float dist[16];
#pragma unroll
        for (int k = 0; k < 8; k++) {
            pxp[k] = pk2(sx[base + 2 * k], sx[base + 2 * k + 1]);
            pyp[k] = pk2(sy[base + 2 * k], sy[base + 2 * k + 1]);
            pzp[k] = pk2(sz[base + 2 * k], sz[base + 2 * k + 1]);
        }
#pragma unroll
        for (int j = 0; j < 16; j++) dist[j] = 1e10f;

        int far = 0;
        float* ob = out_xyz + (size_t)b * NPOINT * 3;

        for (int it = 0; it < NPOINT; it++) {
            float cx = sx[far], cy = sy[far], cz = sz[far];
            if (tid == 0) {
                ob[3 * it] = cx; ob[3 * it + 1] = cy; ob[3 * it + 2] = cz;
                st_rel(g_progress + b, it + 1);     // centroid it is final
            }

            unsigned long long ncx = pk2(-cx, -cx);
            unsigned long long ncy = pk2(-cy, -cy);
            unsigned long long ncz = pk2(-cz, -cz);

            unsigned umax = 0u;
#pragma unroll
            for (int k = 0; k < 8; k++) {
                unsigned long long dx = add2(pxp[k], ncx);   // == px - cx (exact)
                unsigned long long dy = add2(pyp[k], ncy);
                unsigned long long dz = add2(pzp[k], ncz);
                unsigned long long s  = mul2(dx, dx);
                s = add2(s, mul2(dy, dy));
                s = add2(s, mul2(dz, dz));
                float d0, d1;
                upk2(d0, d1, s);
                float n0 = fminf(dist[2 * k],     d0);
                float n1 = fminf(dist[2 * k + 1], d1);
                dist[2 * k]     = n0;
                dist[2 * k + 1] = n1;
                unsigned u0 = __float_as_uint(n0), u1 = __float_as_uint(n1);
                umax = umax > u0 ? umax : u0;
                umax = umax > u1 ? umax : u1;
            }

            unsigned wmax = __reduce_max_sync(0xffffffffu, umax);
            unsigned ball = __ballot_sync(0xffffffffu, umax == wmax);
            int bank = it & 1;
            if (lane == (__ffs(ball) - 1)) {     // lowest lane = lowest index
                int bj = 0;
#pragma unroll
                for (int j = 15; j >= 0; j--)
                    if (__float_as_uint(dist[j]) == wmax) bj = j;
                red_v[bank][w] = wmax;
                red_i[bank][w] = base + bj;
            }
            __syncthreads();
            unsigned v  = red_v[bank][lane & 15];
            int      vi = red_i[bank][lane & 15];
            unsigned m   = __reduce_max_sync(0xffffffffu, v);
            unsigned bal = __ballot_sync(0xffffffffu, v == m);
            far = __shfl_sync(0xffffffffu, vi, __ffs(bal) - 1);
        }
        return;
    }

    // ================= consumer =================
    char* A1 = smem + SM_A1;
    char* A2 = smem + SM_A2;
    char* B1 = smem + SM_B1;
    char* B2 = smem + SM_B2;
    char* B3 = smem + SM_B3;
    float* sb1 = (float*)(smem + SM_SB1);
    float* sb2 = (float*)(smem + SM_SB2);
    float* sb3 = (float*)(smem + SM_SB3);
    int*   pb  = (int*)(smem + SM_PB);
    int*   sidx = (int*)(smem + SM_SIDX);
    float* cc  = (float*)(smem + SM_CC);

    // stage weights/biases once; zero whole A1 (k-pads must be numeric;
    // later tiles leave finite bf16 garbage there, x 0-weights -> exact +-0)
    {
        const uint4* s1 = (const uint4*)g_wb1;
        const uint4* s2 = (const uint4*)g_wb2;
        const uint4* s3 = (const uint4*)g_wb3;
        uint4* d1 = (uint4*)B1; uint4* d2 = (uint4*)B2; uint4* d3 = (uint4*)B3;
        for (int i = tid; i < 1856; i += 512) d1[i] = s1[i];
        for (int i = tid; i < 1600; i += 512) d2[i] = s2[i];
        for (int i = tid; i < 3200; i += 512) d3[i] = s3[i];
        if (tid < 64)  { sb1[tid] = g_fb1[tid]; sb2[tid] = g_fb2[tid]; }
        if (tid < 128)   sb3[tid] = g_fb3[tid];
        uint4 z = {0, 0, 0, 0};
        uint4* a1v = (uint4*)A1;
        for (int i = tid; i < 3712; i += 512) a1v[i] = z;
    }

    int mt = w & 7, nh = w >> 3;
    unsigned aRow = 16 * mt + (lane & 15);
    unsigned aK16 = (lane >> 4) * 16;
    unsigned bLRow = (lane & 7) + ((lane >> 4) << 3);
    unsigned bK16 = ((lane >> 3) & 1) * 16;
    unsigned a1s = (unsigned)__cvta_generic_to_shared(A1);
    unsigned a2s = (unsigned)__cvta_generic_to_shared(A2);
    unsigned b1s = (unsigned)__cvta_generic_to_shared(B1);
    unsigned b2s = (unsigned)__cvta_generic_to_shared(B2);
    unsigned b3s = (unsigned)__cvta_generic_to_shared(B3);

    for (int t = (int)blockIdx.x - BATCH; t < NTILES; t += NCONS) {
        int bb = t >> 9;                              // batch of this tile
        int need = ((4 * t + 3) & (NPOINT - 1)) + 1;  // local centroid count req'd
        if (tid == 0) {
            while (ld_acq(g_progress + bb) < need) __nanosleep(100);
        }
        __syncthreads();       // propagates acquire CTA-wide; guards pb/A1 reuse
        pb[tid] = 0;

        // ---- inline ball query: warp i -> centroid 4t+i (i < 4) ----
        if (w < 4) {
            int g = 4 * t + w;
            const float* cp = out_xyz + (size_t)g * 3;
            float cx = ldcg(cp), cy = ldcg(cp + 1), cz = ldcg(cp + 2);  // L2, skip stale L1
            if (lane == 0) { cc[3 * w] = cx; cc[3 * w + 1] = cy; cc[3 * w + 2] = cz; }
            const float* xb = xyz + (size_t)bb * NPTS * 3;
            const float r2 = (float)(0.2 * 0.2);
            unsigned ltmask = (1u << lane) - 1u;
            int count = 0;
            for (int pbase = 0; pbase < NPTS; pbase += 32) {
                int p = pbase + lane;
                float xv = xb[3 * p], yv = xb[3 * p + 1], zv = xb[3 * p + 2];
                float dx = __fsub_rn(cx, xv);
                float dy = __fsub_rn(cy, yv);
                float dz = __fsub_rn(cz, zv);
                float d  = __fmul_rn(dx, dx);
                d = __fadd_rn(d, __fmul_rn(dy, dy));
                d = __fadd_rn(d, __fmul_rn(dz, dz));
                int in = (d <= r2) ? 1 : 0;
                unsigned m = __ballot_sync(0xffffffffu, in);
                if (in) {
                    int pos = count + __popc(m & ltmask);
                    if (pos < NSAMPLE) sidx[w * NSAMPLE + pos] = p;
                }
                count += __popc(m);
                if (count >= NSAMPLE) break;          // warp-uniform
            }
            __syncwarp();
            int v = (lane < count) ? sidx[w * NSAMPLE + lane] : sidx[w * NSAMPLE];
            sidx[w * NSAMPLE + lane] = v;             // slot0 rewrite is idempotent
        }
        __syncthreads();

        // ---- gather: warp per 8 rows, lane = column ----
        for (int rr = 0; rr < 8; rr++) {
            int r   = (w << 3) + rr;
            int ci  = r >> 5, smp = r & 31;
            int idx = sidx[ci * NSAMPLE + smp];
            const float* pp = xyz + (size_t)(bb * NPTS + idx) * 3;
            const float* pf = feats + (size_t)(bb * NPTS + idx) * 64;
            __nv_bfloat16* row = (__nv_bfloat16*)(A1 + r * 464);

            float v0 = (lane < 3) ? ((pp[lane] - cc[3 * ci + lane]) / 0.2f) : pf[lane - 3];
            float v1 = pf[lane + 29];
            __nv_bfloat16 h0 = __float2bfloat16_rn(v0);
            __nv_bfloat16 l0 = __float2bfloat16_rn(v0 - __bfloat162float(h0));
            __nv_bfloat16 h1 = __float2bfloat16_rn(v1);
            __nv_bfloat16 l1 = __float2bfloat16_rn(v1 - __bfloat162float(h1));
            row[lane]        = h0;  row[lane + 68]  = l0;  row[lane + 136] = h0;
            row[lane + 32]   = h1;  row[lane + 100] = l1;  row[lane + 168] = h1;
            if (lane < 4) {
                float v2 = (lane < 3) ? pf[61 + lane] : 0.0f;
                __nv_bfloat16 h2 = __float2bfloat16_rn(v2);
                __nv_bfloat16 l2 = __float2bfloat16_rn(v2 - __bfloat162float(h2));
                row[64 + lane]  = h2;  row[132 + lane] = l2;  row[200 + lane] = h2;
            }
        }
        __syncthreads();

        float acc[4][4];

        // layer 1
        gemm_4nt<14>(a1s + aRow * 464 + aK16,
                     b1s + (32 * nh + bLRow) * 464 + bK16,
                     b1s + (32 * nh + 16 + bLRow) * 464 + bK16,
                     sb1 + 32 * nh, lane, acc);
        epi_split4(A2, mt, nh, lane, acc);
        __syncthreads();

        // layer 2 -> y2 into A1
        gemm_4nt<12>(a2s + aRow * 400 + aK16,
                     b2s + (32 * nh + bLRow) * 400 + bK16,
                     b2s + (32 * nh + 16 + bLRow) * 400 + bK16,
                     sb2 + 32 * nh, lane, acc);
        epi_split4(A1, mt, nh, lane, acc);
        __syncthreads();

        // layer 3: fused relu + max-pool
        int ci = mt >> 1;
#pragma unroll
        for (int h = 0; h < 2; h++) {
            gemm_4nt<12>(a1s + aRow * 400 + aK16,
                         b3s + (64 * h + 32 * nh + bLRow) * 400 + bK16,
                         b3s + (64 * h + 32 * nh + 16 + bLRow) * 400 + bK16,
                         sb3 + 64 * h + 32 * nh, lane, acc);
#pragma unroll
            for (int ntl = 0; ntl < 4; ntl++) {
                float m0 = fmaxf(fmaxf(acc[ntl][0], acc[ntl][2]), 0.0f);
                float m1 = fmaxf(fmaxf(acc[ntl][1], acc[ntl][3]), 0.0f);
#pragma unroll
                for (int off = 4; off < 32; off <<= 1) {
                    m0 = fmaxf(m0, __shfl_xor_sync(0xffffffffu, m0, off));
                    m1 = fmaxf(m1, __shfl_xor_sync(0xffffffffu, m1, off));
                }
                if (lane < 4) {
                    int col = 64 * h + 32 * nh + 8 * ntl + 2 * lane;
                    atomicMax(&pb[ci * 128 + col],     __float_as_int(m0));
                    atomicMax(&pb[ci * 128 + col + 1], __float_as_int(m1));
                }
            }
        }
        __syncthreads();

        // output: 512 threads == 4*128 values
        {
            int c = tid >> 7, col = tid & 127;
            int g = 4 * t + c;
            out_feats[(size_t)g * 128 + col] = __int_as_float(pb[tid]);
        }
        // loop-top poll + __syncthreads guards pb reset / A1 overwrite
    }
}

// ---------------- launch ----------------
extern "C" void kernel_launch(void* const* d_in, const int* in_sizes, int n_in,
                              void* d_out, int out_size)
{
    const float* xyz   = (const float*)d_in[0];
    const float* feats = (const float*)d_in[1];

    float* out       = (float*)d_out;
    float* out_xyz   = out;                          // [B, NPOINT, 3]
    float* out_feats = out + BATCH * NPOINT * 3;     // [B, NPOINT, 128]

    cudaFuncSetAttribute(fused_kernel, cudaFuncAttributeMaxDynamicSharedMemorySize, SM_TOT);

    prep_kernel<<<32, 256>>>((const float*)d_in[2],  (const float*)d_in[3],
                             (const float*)d_in[4],  (const float*)d_in[5],
                             (const float*)d_in[6],  (const float*)d_in[7],
                             (const float*)d_in[8],  (const float*)d_in[9],
                             (const float*)d_in[10], (const float*)d_in[11],
                             (const float*)d_in[12], (const float*)d_in[13]);

    fused_kernel<<<BATCH + NCONS, 512, SM_TOT>>>(xyz, feats, out_xyz, out_feats);
}

// round 13
// speedup vs baseline: 1.4004x; 1.4004x over previous
#include <cuda_runtime.h>
#include <cuda_bf16.h>
#include <math.h>

#define BATCH   8
#define NPTS    8192
#define NPOINT  2048
#define NSAMPLE 32

#define NCONS   140          // consumer CTAs (grid = 8 + 140 = 148 <= SM count)
#define NTILES  4096         // BATCH*NPOINT/4 centroids per tile
#define PSTRIDE 32           // progress padding: 32 ints = 128B per batch

// ---------------- scratch (no allocation allowed) ----------------
__device__ int g_progress[BATCH * PSTRIDE];   // fps progress, one cache line per batch
// bf16 split weights, K-concatenated [hiB | hiB | loB] (+zero pad), n-major rows
__device__ __align__(16) __nv_bfloat16 g_wb1[64 * 232];   // K'=204 (68x3), stride 232
__device__ __align__(16) __nv_bfloat16 g_wb2[64 * 200];   // K'=192, stride 200
__device__ __align__(16) __nv_bfloat16 g_wb3[128 * 200];
__device__ float g_fb1[64];
__device__ float g_fb2[64];
__device__ float g_fb3[128];

// ---------------- packed f32x2 helpers (per-lane rn => bitwise == scalar) ---
__device__ __forceinline__ unsigned long long pk2(float lo, float hi) {
    unsigned long long r;
    asm("mov.b64 %0, {%1, %2};" : "=l"(r) : "f"(lo), "f"(hi));
    return r;
}
__device__ __forceinline__ void upk2(float& lo, float& hi, unsigned long long v) {
    asm("mov.b64 {%0, %1}, %2;" : "=f"(lo), "=f"(hi) : "l"(v));
}
__device__ __forceinline__ unsigned long long add2(unsigned long long a, unsigned long long b) {
    unsigned long long r;
    asm("add.rn.f32x2 %0, %1, %2;" : "=l"(r) : "l"(a), "l"(b));
    return r;
}
__device__ __forceinline__ unsigned long long mul2(unsigned long long a, unsigned long long b) {
    unsigned long long r;
    asm("mul.rn.f32x2 %0, %1, %2;" : "=l"(r) : "l"(a), "l"(b));
    return r;
}

// ---------------- sync / load helpers ----------------
__device__ __forceinline__ int ld_rlx(const int* p) {
    int v;
    asm volatile("ld.relaxed.gpu.global.b32 %0, [%1];" : "=r"(v) : "l"(p) : "memory");
    return v;
}
__device__ __forceinline__ int ld_acq(const int* p) {
    int v;
    asm volatile("ld.acquire.gpu.global.b32 %0, [%1];" : "=r"(v) : "l"(p) : "memory");
    return v;
}
__device__ __forceinline__ void st_rel(int* p, int v) {
    asm volatile("st.release.gpu.global.b32 [%0], %1;" :: "l"(p), "r"(v) : "memory");
}
__device__ __forceinline__ float ldcg(const float* p) {
    float v;
    asm volatile("ld.global.cg.f32 %0, [%1];" : "=f"(v) : "l"(p));
    return v;
}

// ---------------- mma / ldmatrix helpers ----------------
#define LDSM4(a0,a1,a2,a3,addr) \
    asm volatile("ldmatrix.sync.aligned.m8n8.x4.shared.b16 {%0,%1,%2,%3}, [%4];" \
        : "=r"(a0), "=r"(a1), "=r"(a2), "=r"(a3) : "r"(addr))
#define MMA_BF16(d0,d1,d2,d3,a0,a1,a2,a3,b0,b1) \
    asm volatile("mma.sync.aligned.m16n8k16.row.col.f32.bf16.bf16.f32 " \
        "{%0,%1,%2,%3},{%4,%5,%6,%7},{%8,%9},{%0,%1,%2,%3};" \
        : "+f"(d0), "+f"(d1), "+f"(d2), "+f"(d3) \
        : "r"(a0), "r"(a1), "r"(a2), "r"(a3), "r"(b0), "r"(b1))

// ---------------- fold BN-affine into bf16 hi/lo split weights ----------------
__global__ void prep_kernel(const float* __restrict__ w1, const float* __restrict__ b1,
                            const float* __restrict__ g1, const float* __restrict__ bt1,
                            const float* __restrict__ w2, const float* __restrict__ b2,
                            const float* __restrict__ g2, const float* __restrict__ bt2,
                            const float* __restrict__ w3, const float* __restrict__ b3,
                            const float* __restrict__ g3, const float* __restrict__ bt3)
{
    int t = blockIdx.x * blockDim.x + threadIdx.x;
    int stride = gridDim.x * blockDim.x;
    const float inv = 1.0f / sqrtf(1.0f + 1e-5f);
    for (int i = t; i < BATCH * PSTRIDE; i += stride) g_progress[i] = 0;  // reset each launch
    for (int i = t; i < 64 * 232; i += stride) {
        int o = i / 232, c = i % 232;
        __nv_bfloat16 outv = __float2bfloat16_rn(0.0f);
        if (c < 204) {
            int k = c % 68, seg = c / 68;
            float v = (k < 67) ? (g1[o] * inv) * w1[o * 67 + k] : 0.0f;
            __nv_bfloat16 hi = __float2bfloat16_rn(v);
            if (seg < 2) outv = hi;
            else         outv = __float2bfloat16_rn(v - __bfloat162float(hi));
        }
        g_wb1[i] = outv;
    }
    for (int i = t; i < 64 * 200; i += stride) {
        int o = i / 200, c = i % 200;
        __nv_bfloat16 outv = __float2bfloat16_rn(0.0f);
        if (c < 192) {
            int k = c & 63, seg = c >> 6;
            float v = (g2[o] * inv) * w2[o * 64 + k];
            __nv_bfloat16 hi = __float2bfloat16_rn(v);
            if (seg < 2) outv = hi;
            else         outv = __float2bfloat16_rn(v - __bfloat162float(hi));
        }
        g_wb2[i] = outv;
    }
    for (int i = t; i < 128 * 200; i += stride) {
        int o = i / 200, c = i % 200;
        __nv_bfloat16 outv = __float2bfloat16_rn(0.0f);
        if (c < 192) {
            int k = c & 63, seg = c >> 6;
            float v = (g3[o] * inv) * w3[o * 64 + k];
            __nv_bfloat16 hi = __float2bfloat16_rn(v);
            if (seg < 2) outv = hi;
            else         outv = __float2bfloat16_rn(v - __bfloat162float(hi));
        }
        g_wb3[i] = outv;
    }
    for (int i = t; i < 64; i += stride) {
        g_fb1[i] = (g1[i] * inv) * b1[i] + bt1[i];
        g_fb2[i] = (g2[i] * inv) * b2[i] + bt2[i];
    }
    for (int i = t; i < 128; i += stride)
        g_fb3[i] = (g3[i] * inv) * b3[i] + bt3[i];
}

// ---------------- fused persistent kernel layout ----------------
// smem byte offsets (all 16B aligned). FPS path uses [0, 98304) only.
#define SM_A1   0                    // 128 x 464B (layer1 A), reused stride 400B as y2
#define SM_A2   59392                // 128 x 400B
#define SM_B1   110592               // 64 x 464B
#define SM_B2   140288               // 64 x 400B
#define SM_B3   165888               // 128 x 400B
#define SM_SB1  217088
#define SM_SB2  217344
#define SM_SB3  217600
#define SM_PB   218112               // 4 x 128 int
#define SM_SIDX 220160               // 4 x 32 int (ball indices)
#define SM_CC   220672               // 4 x 3 float centroid coords (+pad)
#define SM_TOT  220736

// K'-loop over this warp's 4 n-tiles (two ldmatrix.x4 B loads per k-step).
template<int KSTEPS>
__device__ __forceinline__ void gemm_4nt(unsigned aAddr, unsigned bAddr0, unsigned bAddr1,
                                         const float* __restrict__ bias, int lane,
                                         float (*acc)[4])
{
    int cp2 = 2 * (lane & 3);
#pragma unroll
    for (int ntl = 0; ntl < 4; ntl++) {
        float bv0 = bias[8 * ntl + cp2];
        float bv1 = bias[8 * ntl + cp2 + 1];
        acc[ntl][0] = bv0; acc[ntl][1] = bv1; acc[ntl][2] = bv0; acc[ntl][3] = bv1;
    }
#pragma unroll
    for (int ks = 0; ks < KSTEPS; ks++) {
        unsigned a0, a1, a2, a3;
        LDSM4(a0, a1, a2, a3, aAddr);
        aAddr += 32;
        unsigned p0, p1, p2, p3, q0, q1, q2, q3;
        LDSM4(p0, p1, p2, p3, bAddr0);  bAddr0 += 32;
        LDSM4(q0, q1, q2, q3, bAddr1);  bAddr1 += 32;
        MMA_BF16(acc[0][0], acc[0][1], acc[0][2], acc[0][3], a0, a1, a2, a3, p0, p1);
        MMA_BF16(acc[1][0], acc[1][1], acc[1][2], acc[1][3], a0, a1, a2, a3, p2, p3);
        MMA_BF16(acc[2][0], acc[2][1], acc[2][2], acc[2][3], a0, a1, a2, a3, q0, q1);
        MMA_BF16(acc[3][0], acc[3][1], acc[3][2], acc[3][3], a0, a1, a2, a3, q2, q3);
    }
}

// relu + bf16 hi/lo re-split + store into next layer's A' (stride 400B).
__device__ __forceinline__ void epi_split4(char* __restrict__ outBase, int mt, int nh,
                                           int lane, float (*acc)[4])
{
    int rr = lane >> 2, cpl = lane & 3;
#pragma unroll
    for (int ntl = 0; ntl < 4; ntl++) {
        int nt = 4 * nh + ntl;
        float v0 = fmaxf(acc[ntl][0], 0.0f), v1 = fmaxf(acc[ntl][1], 0.0f);
        float v2 = fmaxf(acc[ntl][2], 0.0f), v3 = fmaxf(acc[ntl][3], 0.0f);
        __nv_bfloat162 h01 = __floats2bfloat162_rn(v0, v1);
        __nv_bfloat162 h23 = __floats2bfloat162_rn(v2, v3);
        float2 hf01 = __bfloat1622float2(h01);
        float2 hf23 = __bfloat1622float2(h23);
        __nv_bfloat162 l01 = __floats2bfloat162_rn(v0 - hf01.x, v1 - hf01.y);
        __nv_bfloat162 l23 = __floats2bfloat162_rn(v2 - hf23.x, v3 - hf23.y);
        int off0 = (16 * mt + rr) * 400 + (4 * nt + cpl) * 4;
        int off1 = off0 + 8 * 400;
        *(__nv_bfloat162*)(outBase + off0)       = h01;   // hi seg
        *(__nv_bfloat162*)(outBase + off0 + 128) = l01;   // lo seg
        *(__nv_bfloat162*)(outBase + off0 + 256) = h01;   // hi dup
        *(__nv_bfloat162*)(outBase + off1)       = h23;
        *(__nv_bfloat162*)(outBase + off1 + 128) = l23;
        *(__nv_bfloat162*)(outBase + off1 + 256) = h23;
    }
}

// ---------------- fused persistent kernel ----------------
// Blocks 0..7: FPS producers (bitwise-exact; release padded progress word
// after each centroid store). Blocks 8..147: persistent consumers over
// batch-INTERLEAVED tiles t = (u&7)*512 + (u>>3): consumption order matches
// the parallel production order of the 8 batches, and each consumer's ready
// times are monotone (no blocking inversion). Polling: relaxed spin with
// exponential backoff, acquire only on the final confirming load.
__global__ void __launch_bounds__(512, 1)
fused_kernel(const float* __restrict__ xyz, const float* __restrict__ feats,
             float* __restrict__ out_xyz, float* __restrict__ out_feats)
{
    extern __shared__ char smem[];
    __shared__ unsigned red_v[2][16];
    __shared__ int      red_i[2][16];

    int tid = threadIdx.x, lane = tid & 31, w = tid >> 5;

    if (blockIdx.x < BATCH) {
        // ================= FPS producer =================
        float* sx = (float*)smem;
        float* sy = sx + NPTS;
        float* sz = sy + NPTS;
        int b = blockIdx.x;
        const float* xb = xyz + (size_t)b * NPTS * 3;

        for (int p = tid; p < NPTS; p += 512) {
            sx[p] = xb[3 * p];
            sy[p] = xb[3 * p + 1];
            sz[p] = xb[3 * p + 2];
        }
        __syncthreads();

        int base = tid * 16;
        unsigned long long pxp[8], pyp[8], pzp[8];
        float dist[16];
#pragma unroll
        for (int k = 0; k < 8; k++) {
            pxp[k] = pk2(sx[base + 2 * k], sx[base + 2 * k + 1]);
            pyp[k] = pk2(sy[base + 2 * k], sy[base + 2 * k + 1]);
            pzp[k] = pk2(sz[base + 2 * k], sz[base + 2 * k + 1]);
        }
#pragma unroll
        for (int j = 0; j < 16; j++) dist[j] = 1e10f;

        int far = 0;
        float* ob = out_xyz + (size_t)b * NPOINT * 3;

        for (int it = 0; it < NPOINT; it++) {
            float cx = sx[far], cy = sy[far], cz = sz[far];
            if (tid == 0) {
                ob[3 * it] = cx; ob[3 * it + 1] = cy; ob[3 * it + 2] = cz;
                st_rel(g_progress + b * PSTRIDE, it + 1);   // centroid it final
            }

            unsigned long long ncx = pk2(-cx, -cx);
            unsigned long long ncy = pk2(-cy, -cy);
            unsigned long long ncz = pk2(-cz, -cz);

            unsigned umax = 0u;
#pragma unroll
            for (int k = 0; k < 8; k++) {
                unsigned long long dx = add2(pxp[k], ncx);   // == px - cx (exact)
                unsigned long long dy = add2(pyp[k], ncy);
                unsigned long long dz = add2(pzp[k], ncz);
                unsigned long long s  = mul2(dx, dx);
                s = add2(s, mul2(dy, dy));
                s = add2(s, mul2(dz, dz));
                float d0, d1;
                upk2(d0, d1, s);
                float n0 = fminf(dist[2 * k],     d0);
                float n1 = fminf(dist[2 * k + 1], d1);
                dist[2 * k]     = n0;
                dist[2 * k + 1] = n1;
                unsigned u0 = __float_as_uint(n0), u1 = __float_as_uint(n1);
                umax = umax > u0 ? umax : u0;
                umax = umax > u1 ? umax : u1;
            }

            unsigned wmax = __reduce_max_sync(0xffffffffu, umax);
            unsigned ball = __ballot_sync(0xffffffffu, umax == wmax);
            int bank = it & 1;
            if (lane == (__ffs(ball) - 1)) {     // lowest lane = lowest index
                int bj = 0;
#pragma unroll
                for (int j = 15; j >= 0; j--)
                    if (__float_as_uint(dist[j]) == wmax) bj = j;
                red_v[bank][w] = wmax;
                red_i[bank][w] = base + bj;
            }
            __syncthreads();
            unsigned v  = red_v[bank][lane & 15];
            int      vi = red_i[bank][lane & 15];
            unsigned m   = __reduce_max_sync(0xffffffffu, v);
            unsigned bal = __ballot_sync(0xffffffffu, v == m);
            far = __shfl_sync(0xffffffffu, vi, __ffs(bal) - 1);
        }
        return;
    }

    // ================= consumer =================
    char* A1 = smem + SM_A1;
    char* A2 = smem + SM_A2;
    char* B1 = smem + SM_B1;
    char* B2 = smem + SM_B2;
    char* B3 = smem + SM_B3;
    float* sb1 = (float*)(smem + SM_SB1);
    float* sb2 = (float*)(smem + SM_SB2);
    float* sb3 = (float*)(smem + SM_SB3);
    int*   pb  = (int*)(smem + SM_PB);
    int*   sidx = (int*)(smem + SM_SIDX);
    float* cc  = (float*)(smem + SM_CC);

    // stage weights/biases once; zero whole A1 (k-pads must be numeric;
    // later tiles leave finite bf16 garbage there, x 0-weights -> exact +-0)
    {
        const uint4* s1 = (const uint4*)g_wb1;
        const uint4* s2 = (const uint4*)g_wb2;
        const uint4* s3 = (const uint4*)g_wb3;
        uint4* d1 = (uint4*)B1; uint4* d2 = (uint4*)B2; uint4* d3 = (uint4*)B3;
        for (int i = tid; i < 1856; i += 512) d1[i] = s1[i];
        for (int i = tid; i < 1600; i += 512) d2[i] = s2[i];
        for (int i = tid; i < 3200; i += 512) d3[i] = s3[i];
        if (tid < 64)  { sb1[tid] = g_fb1[tid]; sb2[tid] = g_fb2[tid]; }
        if (tid < 128)   sb3[tid] = g_fb3[tid];
        uint4 z = {0, 0, 0, 0};
        uint4* a1v = (uint4*)A1;
        for (int i = tid; i < 3712; i += 512) a1v[i] = z;
    }

    int mt = w & 7, nh = w >> 3;
    unsigned aRow = 16 * mt + (lane & 15);
    unsigned aK16 = (lane >> 4) * 16;
    unsigned bLRow = (lane & 7) + ((lane >> 4) << 3);
    unsigned bK16 = ((lane >> 3) & 1) * 16;
    unsigned a1s = (unsigned)__cvta_generic_to_shared(A1);
    unsigned a2s = (unsigned)__cvta_generic_to_shared(A2);
    unsigned b1s = (unsigned)__cvta_generic_to_shared(B1);
    unsigned b2s = (unsigned)__cvta_generic_to_shared(B2);
    unsigned b3s = (unsigned)__cvta_generic_to_shared(B3);

    for (int u = (int)blockIdx.x - BATCH; u < NTILES; u += NCONS) {
        int t  = ((u & 7) << 9) | (u >> 3);           // batch-interleaved tile
        int bb = u & 7;                               // == t >> 9
        int jj = u >> 3;                              // batch-local tile index
        int need = 4 * jj + 4;                        // centroids required
        if (tid == 0) {
            const int* pp = g_progress + bb * PSTRIDE;
            if (ld_rlx(pp) < need) {
                int ns = 256;
                do {
                    __nanosleep(ns);
                    if (ns < 4096) ns <<= 1;
                } while (ld_rlx(pp) < need);
            }
            while (ld_acq(pp) < need) __nanosleep(256);   // ordering
        }
        __syncthreads();       // propagates acquire CTA-wide; guards pb/A1 reuse
        pb[tid] = 0;

        // ---- inline ball query: warp i -> centroid 4t+i (i < 4) ----
        if (w < 4) {
            int g = 4 * t + w;
            const float* cp = out_xyz + (size_t)g * 3;
            float cx = ldcg(cp), cy = ldcg(cp + 1), cz = ldcg(cp + 2);  // L2, skip stale L1
            if (lane == 0) { cc[3 * w] = cx; cc[3 * w + 1] = cy; cc[3 * w + 2] = cz; }
            const float* xb = xyz + (size_t)bb * NPTS * 3;
            const float r2 = (float)(0.2 * 0.2);
            unsigned ltmask = (1u << lane) - 1u;
            int count = 0;
            for (int pbase = 0; pbase < NPTS; pbase += 32) {
                int p = pbase + lane;
                float xv = xb[3 * p], yv = xb[3 * p + 1], zv = xb[3 * p + 2];
                float dx = __fsub_rn(cx, xv);
                float dy = __fsub_rn(cy, yv);
                float dz = __fsub_rn(cz, zv);
                float d  = __fmul_rn(dx, dx);
                d = __fadd_rn(d, __fmul_rn(dy, dy));
                d = __fadd_rn(d, __fmul_rn(dz, dz));
                int in = (d <= r2) ? 1 : 0;
                unsigned m = __ballot_sync(0xffffffffu, in);
                if (in) {
                    int pos = count + __popc(m & ltmask);
                    if (pos < NSAMPLE) sidx[w * NSAMPLE + pos] = p;
                }
                count += __popc(m);
                if (count >= NSAMPLE) break;          // warp-uniform
            }
            __syncwarp();
            int v = (lane < count) ? sidx[w * NSAMPLE + lane] : sidx[w * NSAMPLE];
            sidx[w * NSAMPLE + lane] = v;             // slot0 rewrite is idempotent
        }
        __syncthreads();

        // ---- gather: warp per 8 rows, lane = column ----
        for (int rr = 0; rr < 8; rr++) {
            int r   = (w << 3) + rr;
            int ci  = r >> 5, smp = r & 31;
            int idx = sidx[ci * NSAMPLE + smp];
            const float* pp = xyz + (size_t)(bb * NPTS + idx) * 3;
            const float* pf = feats + (size_t)(bb * NPTS + idx) * 64;
            __nv_bfloat16* row = (__nv_bfloat16*)(A1 + r * 464);

            float v0 = (lane < 3) ? ((pp[lane] - cc[3 * ci + lane]) / 0.2f) : pf[lane - 3];
            float v1 = pf[lane + 29];
            __nv_bfloat16 h0 = __float2bfloat16_rn(v0);
            __nv_bfloat16 l0 = __float2bfloat16_rn(v0 - __bfloat162float(h0));
            __nv_bfloat16 h1 = __float2bfloat16_rn(v1);
            __nv_bfloat16 l1 = __float2bfloat16_rn(v1 - __bfloat162float(h1));
            row[lane]        = h0;  row[lane + 68]  = l0;  row[lane + 136] = h0;
            row[lane + 32]   = h1;  row[lane + 100] = l1;  row[lane + 168] = h1;
            if (lane < 4) {
                float v2 = (lane < 3) ? pf[61 + lane] : 0.0f;
                __nv_bfloat16 h2 = __float2bfloat16_rn(v2);
                __nv_bfloat16 l2 = __float2bfloat16_rn(v2 - __bfloat162float(h2));
                row[64 + lane]  = h2;  row[132 + lane] = l2;  row[200 + lane] = h2;
            }
        }
        __syncthreads();

        float acc[4][4];

        // layer 1
        gemm_4nt<14>(a1s + aRow * 464 + aK16,
                     b1s + (32 * nh + bLRow) * 464 + bK16,
                     b1s + (32 * nh + 16 + bLRow) * 464 + bK16,
                     sb1 + 32 * nh, lane, acc);
        epi_split4(A2, mt, nh, lane, acc);
        __syncthreads();

        // layer 2 -> y2 into A1
        gemm_4nt<12>(a2s + aRow * 400 + aK16,
                     b2s + (32 * nh + bLRow) * 400 + bK16,
                     b2s + (32 * nh + 16 + bLRow) * 400 + bK16,
                     sb2 + 32 * nh, lane, acc);
        epi_split4(A1, mt, nh, lane, acc);
        __syncthreads();

        // layer 3: fused relu + max-pool
        int ci = mt >> 1;
#pragma unroll
        for (int h = 0; h < 2; h++) {
            gemm_4nt<12>(a1s + aRow * 400 + aK16,
                         b3s + (64 * h + 32 * nh + bLRow) * 400 + bK16,
                         b3s + (64 * h + 32 * nh + 16 + bLRow) * 400 + bK16,
                         sb3 + 64 * h + 32 * nh, lane, acc);
#pragma unroll
            for (int ntl = 0; ntl < 4; ntl++) {
                float m0 = fmaxf(fmaxf(acc[ntl][0], acc[ntl][2]), 0.0f);
                float m1 = fmaxf(fmaxf(acc[ntl][1], acc[ntl][3]), 0.0f);
#pragma unroll
                for (int off = 4; off < 32; off <<= 1) {
                    m0 = fmaxf(m0, __shfl_xor_sync(0xffffffffu, m0, off));
                    m1 = fmaxf(m1, __shfl_xor_sync(0xffffffffu, m1, off));
                }
                if (lane < 4) {
                    int col = 64 * h + 32 * nh + 8 * ntl + 2 * lane;
                    atomicMax(&pb[ci * 128 + col],     __float_as_int(m0));
                    atomicMax(&pb[ci * 128 + col + 1], __float_as_int(m1));
                }
            }
        }
        __syncthreads();

        // output: 512 threads == 4*128 values
        {
            int c = tid >> 7, col = tid & 127;
            int g = 4 * t + c;
            out_feats[(size_t)g * 128 + col] = __int_as_float(pb[tid]);
        }
        // loop-top poll + __syncthreads guards pb reset / A1 overwrite
    }
}

// ---------------- launch ----------------
extern "C" void kernel_launch(void* const* d_in, const int* in_sizes, int n_in,
                              void* d_out, int out_size)
{
    const float* xyz   = (const float*)d_in[0];
    const float* feats = (const float*)d_in[1];

    float* out       = (float*)d_out;
    float* out_xyz   = out;                          // [B, NPOINT, 3]
    float* out_feats = out + BATCH * NPOINT * 3;     // [B, NPOINT, 128]

    cudaFuncSetAttribute(fused_kernel, cudaFuncAttributeMaxDynamicSharedMemorySize, SM_TOT);

    prep_kernel<<<32, 256>>>((const float*)d_in[2],  (const float*)d_in[3],
                             (const float*)d_in[4],  (const float*)d_in[5],
                             (const float*)d_in[6],  (const float*)d_in[7],
                             (const float*)d_in[8],  (const float*)d_in[9],
                             (const float*)d_in[10], (const float*)d_in[11],
                             (const float*)d_in[12], (const float*)d_in[13]);

    fused_kernel<<<BATCH + NCONS, 512, SM_TOT>>>(xyz, feats, out_xyz, out_feats);
}